// round 1
// baseline (speedup 1.0000x reference)
#include <cuda_runtime.h>
#include <math.h>

#define S_DIM 2048
#define B_DIM 32
#define H_DIM 1024
#define K_DIM 2048                 // 2*H
#define M_DIM (S_DIM * B_DIM)      // 65536

#define BM 128
#define BN 128
#define BK 16
#define NCHUNKS (H_DIM / BN)       // 8

// Scratch (no allocations allowed in kernel_launch)
__device__ float g_hproj[B_DIM * H_DIM];
__device__ float g_scores[B_DIM * S_DIM];

typedef unsigned long long u64;

__device__ __forceinline__ u64 pack2(float lo, float hi) {
    u64 r;
    asm("mov.b64 %0, {%1, %2};" : "=l"(r) : "f"(lo), "f"(hi));
    return r;
}
__device__ __forceinline__ void unpack2(u64 v, float& lo, float& hi) {
    asm("mov.b64 {%0, %1}, %2;" : "=f"(lo), "=f"(hi) : "l"(v));
}
// Packed fp32x2 FMA (Blackwell FFMA2 — only reachable via PTX fma.rn.f32x2)
__device__ __forceinline__ void fma2(u64& d, u64 a, u64 b) {
    asm("fma.rn.f32x2 %0, %1, %2, %3;" : "=l"(d) : "l"(a), "l"(b), "l"(d));
}

// ---------------------------------------------------------------------------
// Kernel 1: h_proj[b][h] = bias[h] + sum_e hidden[b][e] * W[e][h]   (Wh = W[:H])
// ---------------------------------------------------------------------------
__global__ void hproj_kernel(const float* __restrict__ hidden,
                             const float* __restrict__ W,
                             const float* __restrict__ bias) {
    int g = blockIdx.x * blockDim.x + threadIdx.x;   // 0..32767
    int b = g >> 10;
    int h = g & 1023;
    const float* hrow = hidden + b * H_DIM;
    float acc = bias[h];
#pragma unroll 8
    for (int e = 0; e < H_DIM; e++)
        acc += hrow[e] * W[(size_t)e * H_DIM + h];
    g_hproj[g] = acc;
}

// ---------------------------------------------------------------------------
// Kernel 2: fused  scores[b][s] = sum_h v[h] * tanh( (enc_row @ We)[h] + hproj[b][h] )
// GEMM: M=65536 rows (row = s*32+b), K=2048, N=1024. N is looped in 8 chunks of 128;
// the C tile never leaves registers.
// ---------------------------------------------------------------------------
__global__ __launch_bounds__(256, 2)
void score_kernel(const float* __restrict__ enc,
                  const float* __restrict__ W,
                  const float* __restrict__ v) {
    __shared__ float As[BK][BM];   // A transposed: As[k][m]
    __shared__ float Bs[BK][BN];   // Bs[k][n]

    const int t  = threadIdx.x;
    const int tx = t & 15;         // n direction (16)
    const int ty = t >> 4;         // m direction (16)
    const int bm = blockIdx.x * BM;
    const float* Wp = W + (size_t)H_DIM * H_DIM;   // We base: W[(H+e)*H + n]

    float rs[8];
#pragma unroll
    for (int i = 0; i < 8; i++) rs[i] = 0.f;

    for (int nc = 0; nc < NCHUNKS; nc++) {
        const int n0 = nc * BN;
        u64 acc[8][4];
#pragma unroll
        for (int i = 0; i < 8; i++)
#pragma unroll
            for (int j = 0; j < 4; j++) acc[i][j] = 0ull;

        for (int k0 = 0; k0 < K_DIM; k0 += BK) {
            __syncthreads();
            // Load A tile: 128 rows x 16 k  (512 float4, 2 per thread), store transposed
#pragma unroll
            for (int it = 0; it < 2; it++) {
                int idx = t + it * 256;
                int i  = idx >> 2;
                int kq = idx & 3;
                float4 va = *reinterpret_cast<const float4*>(
                    &enc[(size_t)(bm + i) * K_DIM + k0 + kq * 4]);
                As[kq * 4 + 0][i] = va.x;
                As[kq * 4 + 1][i] = va.y;
                As[kq * 4 + 2][i] = va.z;
                As[kq * 4 + 3][i] = va.w;
            }
            // Load B tile: 16 k x 128 n (512 float4, 2 per thread)
#pragma unroll
            for (int it = 0; it < 2; it++) {
                int idx = t + it * 256;
                int k  = idx >> 5;
                int nq = idx & 31;
                *reinterpret_cast<float4*>(&Bs[k][nq * 4]) =
                    *reinterpret_cast<const float4*>(
                        &Wp[(size_t)(k0 + k) * H_DIM + n0 + nq * 4]);
            }
            __syncthreads();

#pragma unroll
            for (int k = 0; k < BK; k++) {
                float4 a0 = *reinterpret_cast<const float4*>(&As[k][ty * 8]);
                float4 a1 = *reinterpret_cast<const float4*>(&As[k][ty * 8 + 4]);
                u64 a2[8];
                a2[0] = pack2(a0.x, a0.x);
                a2[1] = pack2(a0.y, a0.y);
                a2[2] = pack2(a0.z, a0.z);
                a2[3] = pack2(a0.w, a0.w);
                a2[4] = pack2(a1.x, a1.x);
                a2[5] = pack2(a1.y, a1.y);
                a2[6] = pack2(a1.z, a1.z);
                a2[7] = pack2(a1.w, a1.w);
                const u64* bp = reinterpret_cast<const u64*>(&Bs[k][tx * 8]);
                u64 b2[4] = {bp[0], bp[1], bp[2], bp[3]};
#pragma unroll
                for (int i = 0; i < 8; i++)
#pragma unroll
                    for (int j = 0; j < 4; j++)
                        fma2(acc[i][j], a2[i], b2[j]);
            }
        }

        // Epilogue for this N chunk: tanh + weighted reduce over the 128 n's
#pragma unroll
        for (int i = 0; i < 8; i++) {
            int r = bm + ty * 8 + i;
            int b = r & 31;
            const float* hp = g_hproj + (size_t)b * H_DIM + n0 + tx * 8;
            const float* vp = v + n0 + tx * 8;
            float s = 0.f;
#pragma unroll
            for (int j = 0; j < 4; j++) {
                float c0, c1;
                unpack2(acc[i][j], c0, c1);
                s += vp[j * 2]     * tanhf(c0 + hp[j * 2]);
                s += vp[j * 2 + 1] * tanhf(c1 + hp[j * 2 + 1]);
            }
            // Butterfly reduce across the 16 tx lanes (stays inside half-warp)
#pragma unroll
            for (int off = 8; off > 0; off >>= 1)
                s += __shfl_xor_sync(0xffffffffu, s, off);
            rs[i] += s;
        }
    }

    if (tx == 0) {
#pragma unroll
        for (int i = 0; i < 8; i++) {
            int r = bm + ty * 8 + i;            // r = s*32 + b
            g_scores[(r & 31) * S_DIM + (r >> 5)] = rs[i];
        }
    }
}

// ---------------------------------------------------------------------------
// Kernel 3: row softmax over S for each of the 32 batch rows
// ---------------------------------------------------------------------------
__global__ void softmax_kernel(float* __restrict__ out) {
    __shared__ float red[256];
    const int b = blockIdx.x;
    const int t = threadIdx.x;
    const float* row = g_scores + (size_t)b * S_DIM;
    float* orow = out + (size_t)b * S_DIM;

    float m = -INFINITY;
    for (int i = t; i < S_DIM; i += 256) m = fmaxf(m, row[i]);
    red[t] = m;
    __syncthreads();
    for (int o = 128; o > 0; o >>= 1) {
        if (t < o) red[t] = fmaxf(red[t], red[t + o]);
        __syncthreads();
    }
    m = red[0];
    __syncthreads();

    float sum = 0.f;
    for (int i = t; i < S_DIM; i += 256) {
        float e = expf(row[i] - m);
        orow[i] = e;
        sum += e;
    }
    red[t] = sum;
    __syncthreads();
    for (int o = 128; o > 0; o >>= 1) {
        if (t < o) red[t] += red[t + o];
        __syncthreads();
    }
    float inv = 1.f / red[0];
    __syncthreads();
    for (int i = t; i < S_DIM; i += 256) orow[i] *= inv;
}

// ---------------------------------------------------------------------------
extern "C" void kernel_launch(void* const* d_in, const int* in_sizes, int n_in,
                              void* d_out, int out_size) {
    const float* hidden = (const float*)d_in[0];   // (B, H)
    const float* enc    = (const float*)d_in[1];   // (S, B, 2H)
    const float* W      = (const float*)d_in[2];   // (3H, H)
    const float* bias   = (const float*)d_in[3];   // (H,)
    const float* v      = (const float*)d_in[4];   // (H,)
    float* out = (float*)d_out;                    // (B, S)

    hproj_kernel<<<(B_DIM * H_DIM) / 256, 256>>>(hidden, W, bias);
    score_kernel<<<M_DIM / BM, 256>>>(enc, W, v);
    softmax_kernel<<<B_DIM, 256>>>(out);
}